// round 13
// baseline (speedup 1.0000x reference)
#include <cuda_runtime.h>
#include <cstdint>
#include <cstddef>

// Problem constants
#define B_      64
#define T_      1024
#define F_      256
#define U_      512
#define G3_     1536
#define SIG_    31

// Persistent kernel config
#define GRID_    128         // CTAs; each owns 4 units
#define THREADS_ 512
#define KTOT_    768         // K = 256 (x) + 512 (h)
#define NCOL_    12          // 3 gates x 4 units per CTA
#define NJP_     6           // column pairs per CTA
#define RGRP_    16          // reduction groups after shuffle fold
#define WROW_    12          // w2 floats per k-row (NON-duplicated)
#define FB_      (F_ * B_)
#define UB_      (U_ * B_)
#define RSZ_     (RGRP_ * NJP_ * B_ * 2)   // floats per rs buffer (12288)
#define NBAR_    16          // barrier groups (8 CTAs each)

// Scratch (static __device__ arrays: no allocation)
__device__ __align__(256) float g_f_all[(size_t)T_ * UB_]; // sigmoid(f_pre) [t][u][b]
__device__ __align__(256) float g_x[(size_t)T_ * FB_];     // x transposed [t][f][b]
__device__ __align__(256) float g_h[2][UB_];               // ping-pong h [u][b]
__device__ __align__(128) unsigned int g_bars[NBAR_];      // decentralized barriers

__device__ __forceinline__ void fma2(unsigned long long& a, unsigned long long x,
                                     unsigned long long w) {
    asm("fma.rn.f32x2 %0, %1, %2, %0;" : "+l"(a) : "l"(x), "l"(w));
}
__device__ __forceinline__ unsigned long long pack2(float x) {
    unsigned long long r; asm("mov.b64 %0, {%1, %1};" : "=l"(r) : "f"(x)); return r;
}
__device__ __forceinline__ float2 up2(unsigned long long v) {
    float2 r; asm("mov.b64 {%0, %1}, %2;" : "=f"(r.x), "=f"(r.y) : "l"(v)); return r;
}
__device__ __forceinline__ float tanh_fast(float x) {
    float y; asm("tanh.approx.f32 %0, %1;" : "=f"(y) : "f"(x)); return y;
}
__device__ __forceinline__ float sigmoid_fast(float x) {
    return 0.5f * tanh_fast(0.5f * x) + 0.5f;
}

// 24 packed FMAs for one k-row: activation float4 (4 batches) x 12 cols (6 pairs)
#define ROW_FMA(AV, WROWP)                                                     \
{                                                                              \
    const ulonglong2* wr_ = (const ulonglong2*)(WROWP);                        \
    ulonglong2 wA_ = wr_[0], wB_ = wr_[1], wC_ = wr_[2];                       \
    unsigned long long a0_ = pack2((AV).x), a1_ = pack2((AV).y);               \
    unsigned long long a2_ = pack2((AV).z), a3_ = pack2((AV).w);               \
    fma2(acc[0][0], a0_, wA_.x); fma2(acc[0][1], a1_, wA_.x);                  \
    fma2(acc[0][2], a2_, wA_.x); fma2(acc[0][3], a3_, wA_.x);                  \
    fma2(acc[1][0], a0_, wA_.y); fma2(acc[1][1], a1_, wA_.y);                  \
    fma2(acc[1][2], a2_, wA_.y); fma2(acc[1][3], a3_, wA_.y);                  \
    fma2(acc[2][0], a0_, wB_.x); fma2(acc[2][1], a1_, wB_.x);                  \
    fma2(acc[2][2], a2_, wB_.x); fma2(acc[2][3], a3_, wB_.x);                  \
    fma2(acc[3][0], a0_, wB_.y); fma2(acc[3][1], a1_, wB_.y);                  \
    fma2(acc[3][2], a2_, wB_.y); fma2(acc[3][3], a3_, wB_.y);                  \
    fma2(acc[4][0], a0_, wC_.x); fma2(acc[4][1], a1_, wC_.x);                  \
    fma2(acc[4][2], a2_, wC_.x); fma2(acc[4][3], a3_, wC_.x);                  \
    fma2(acc[5][0], a0_, wC_.y); fma2(acc[5][1], a1_, wC_.y);                  \
    fma2(acc[5][2], a2_, wC_.y); fma2(acc[5][3], a3_, wC_.y);                  \
}

// fpre: f_all[t][u][b] = sigmoid(sig . fk + b_f); transposes x to g_x[t][f][b];
// resets barrier counters + initial h each launch (graph replays).
__global__ void fpre_kernel(const float* __restrict__ inputs,
                            const float* __restrict__ sig,
                            const float* __restrict__ fk,
                            const float* __restrict__ bias) {
    extern __shared__ float xs[];            // [256][65] transpose tile
    __shared__ float sig_s[B_][33];
    const int t = blockIdx.x, tid = threadIdx.x;
    if (t == 0 && tid < NBAR_) g_bars[tid] = 0u;
    if (t < 128) g_h[0][t * 256 + tid] = 0.f;

    for (int i = tid; i < B_ * F_; i += 256) {
        int b = i >> 8, f = i & 255;
        xs[f * 65 + b] = inputs[((size_t)b * T_ + t) * F_ + f];
    }
    for (int i = tid; i < B_ * SIG_; i += 256) {
        int b = i / SIG_, d = i - b * SIG_;
        sig_s[b][d] = sig[((size_t)b * T_ + t) * SIG_ + d];
    }
    __syncthreads();
    for (int j = tid; j < FB_; j += 256) {
        int f = j >> 6, b = j & 63;
        g_x[(size_t)t * FB_ + j] = xs[f * 65 + b];
    }
    size_t base = (size_t)t * UB_;
    for (int idx = tid; idx < UB_; idx += 256) {
        int u = idx >> 6, b = idx & 63;
        float acc = bias[U_ + u];
        #pragma unroll
        for (int d = 0; d < SIG_; d++) acc += sig_s[b][d] * __ldg(&fk[d * U_ + u]);
        g_f_all[base + idx] = 1.f / (1.f + expf(-acc));
    }
}

// Persistent recurrence with DECENTRALIZED barriers: warp w consumes h rows
// [32w,32w+32) produced by CTAs [8w,8w+8); it polls only g_bars[w]. No global
// phase-A sync; one __syncthreads per step (rs visibility) + bar1 (h stores).
__global__ void __launch_bounds__(THREADS_, 1)
lstm_kernel(const float* __restrict__ ik, const float* __restrict__ rk,
            const float* __restrict__ bias, float* __restrict__ out) {
    extern __shared__ float smem[];
    float* w2  = smem;                         // [768][12] weights (36864 B)
    float* rs0 = smem + KTOT_ * WROW_;         // rs parity 0 (49152 B)
    float* rs1 = rs0 + RSZ_;                   // rs parity 1 (49152 B)

    const int tid  = threadIdx.x;
    const int ublk = blockIdx.x * 4;

    // Weights (non-duplicated): rows 0..255 = input_kernel, 256..767 = recurrent.
    for (int idx = tid; idx < KTOT_ * NCOL_; idx += THREADS_) {
        int k = idx / NCOL_, j = idx - k * NCOL_;
        int col = (j >> 2) * U_ + ublk + (j & 3);
        w2[idx] = (k < F_) ? ik[(size_t)k * G3_ + col]
                           : rk[(size_t)(k - F_) * G3_ + col];
    }

    const int b4 = tid & 15;            // batch group (4 batches)
    const int ks = tid >> 4;            // 0..31 K-split
    const int wq = tid >> 5;            // warp index == barrier group consumed
    const int fb = tid & 63, fu = (tid >> 6) & 3;
    const int u_g = ublk + fu;
    float bi = 0.f, bc = 0.f, bo = 0.f;
    if (tid < 256) {
        bi = bias[u_g]; bc = bias[2 * U_ + u_g]; bo = bias[3 * U_ + u_g];
    }
    const int fjp = fu >> 1, fcomp = fu & 1;
    unsigned int* mybar  = &g_bars[wq];
    unsigned int* arrbar = &g_bars[blockIdx.x >> 3];

    const float* xbase = g_x + (size_t)(ks * 8) * B_ + b4 * 4;     // + t*FB_
    const int    hoff  = (ks * 16) * B_ + b4 * 4;                  // within g_h[p]
    const float* wx    = w2 + (ks * 8) * WROW_;
    const float* wh    = w2 + (F_ + ks * 16) * WROW_;

    float c_state = 0.f;
    float fval = (tid < 256) ? __ldg(&g_f_all[(size_t)u_g * B_ + fb]) : 0.f;
    __syncthreads();   // weights visible

    for (int t = 0; t < T_; t++) {
        unsigned long long acc[NJP_][4];
        #pragma unroll
        for (int j = 0; j < NJP_; j++) {
            acc[j][0] = 0ull; acc[j][1] = 0ull; acc[j][2] = 0ull; acc[j][3] = 0ull;
        }

        const float* xp = xbase + (size_t)t * FB_;
        const float* hp = g_h[t & 1] + hoff;
        float* rs = (t & 1) ? rs1 : rs0;

        // ---- Phase A: x loads + first 4 x rows (no sync, no global poll) ----
        float4 xv[8];
        #pragma unroll
        for (int j = 0; j < 8; j++) xv[j] = __ldg((const float4*)(xp + j * B_));
        #pragma unroll
        for (int j = 0; j < 4; j++) ROW_FMA(xv[j], wx + j * WROW_)

        // ---- per-warp poll: wait for THIS warp's 8 producer CTAs only ----
        if (t > 0) {
            const unsigned tgt = (unsigned)t * 8u;
            unsigned v;
            do {
                asm volatile("ld.acquire.gpu.global.u32 %0, [%1];"
                             : "=r"(v) : "l"(mybar) : "memory");
            } while (v < tgt);
        }

        // ---- Phase B: issue h loads, consume rest of x, then h ----
        float4 hv0[8], hv1[8];
        #pragma unroll
        for (int j = 0; j < 8; j++) hv0[j] = __ldcg((const float4*)(hp + j * B_));
        #pragma unroll
        for (int j = 0; j < 8; j++) hv1[j] = __ldcg((const float4*)(hp + (8 + j) * B_));
        #pragma unroll
        for (int j = 4; j < 8; j++) ROW_FMA(xv[j], wx + j * WROW_)
        #pragma unroll
        for (int j = 0; j < 8; j++) ROW_FMA(hv0[j], wh + j * WROW_)
        #pragma unroll
        for (int j = 0; j < 8; j++) ROW_FMA(hv1[j], wh + (8 + j) * WROW_)

        // ---- Phase C: shuffle-fold ks pairs (lane^16), store 16 groups ----
        #pragma unroll
        for (int jp = 0; jp < NJP_; jp++) {
            #pragma unroll
            for (int b = 0; b < 4; b++) {
                float2 v = up2(acc[jp][b]);
                v.x += __shfl_xor_sync(0xffffffffu, v.x, 16);
                v.y += __shfl_xor_sync(0xffffffffu, v.y, 16);
                if ((ks & 1) == 0)
                    *(float2*)&rs[(((ks >> 1) * NJP_ + jp) * B_ + b4 * 4 + b) * 2] = v;
            }
        }
        __syncthreads();   // rs visible; also joins all warps' polls (WAR safety)

        // ---- Phase D: finalize (tid<256); others run ahead into next x-part ----
        if (tid < 256) {
            float si = 0.f, sc = 0.f, so = 0.f;
            #pragma unroll
            for (int p = 0; p < RGRP_; p++) {
                si += rs[((p * NJP_     + fjp) * B_ + fb) * 2 + fcomp];
                sc += rs[((p * NJP_ + 2 + fjp) * B_ + fb) * 2 + fcomp];
                so += rs[((p * NJP_ + 4 + fjp) * B_ + fb) * 2 + fcomp];
            }
            float ig = sigmoid_fast(si + bi);
            float cg = tanh_fast(sc + bc);
            float og = sigmoid_fast(so + bo);
            c_state = fval * c_state + ig * cg;
            float h = og * tanh_fast(c_state);
            if (t == T_ - 1) {
                out[fb * U_ + u_g] = h;
            } else {
                g_h[(t + 1) & 1][u_g * B_ + fb] = h;
                fval = __ldg(&g_f_all[(size_t)(t + 1) * UB_ + u_g * B_ + fb]);
                asm volatile("bar.sync 1, 256;" ::: "memory");  // all h stores done
                if (tid == 0) {
                    asm volatile("red.release.gpu.global.add.u32 [%0], %1;"
                                 :: "l"(arrbar), "r"(1u) : "memory");
                }
            }
        }
        // GEMM-only warps fall straight into step t+1 phase A; their h access
        // is gated by their own per-warp poll.
    }
}

extern "C" void kernel_launch(void* const* d_in, const int* in_sizes, int n_in,
                              void* d_out, int out_size) {
    const float* inputs = (const float*)d_in[0];  // [64,1024,256]
    const float* sig    = (const float*)d_in[1];  // [64,1024,31]
    const float* fk     = (const float*)d_in[2];  // [31,512]
    const float* ik     = (const float*)d_in[3];  // [256,1536]
    const float* rk     = (const float*)d_in[4];  // [512,1536]
    const float* bias   = (const float*)d_in[5];  // [2048]
    float* out = (float*)d_out;                   // [64,512]
    (void)in_sizes; (void)n_in; (void)out_size;

    const int fpre_smem = 256 * 65 * 4;
    cudaFuncSetAttribute(fpre_kernel, cudaFuncAttributeMaxDynamicSharedMemorySize,
                         fpre_smem);
    const int smem_bytes = (KTOT_ * WROW_ + 2 * RSZ_) * 4;  // 135168 B
    cudaFuncSetAttribute(lstm_kernel, cudaFuncAttributeMaxDynamicSharedMemorySize,
                         smem_bytes);

    fpre_kernel<<<T_, 256, fpre_smem>>>(inputs, sig, fk, bias);
    lstm_kernel<<<GRID_, THREADS_, smem_bytes>>>(ik, rk, bias, out);
}

// round 14
// speedup vs baseline: 1.2815x; 1.2815x over previous
#include <cuda_runtime.h>
#include <cstdint>
#include <cstddef>

// Problem constants
#define B_      64
#define T_      1024
#define F_      256
#define U_      512
#define G3_     1536
#define SIG_    31

// Persistent kernel config
#define GRID_    128         // CTAs; each owns 4 units
#define THREADS_ 512
#define KTOT_    768         // K = 256 (x) + 512 (h)
#define NCOL_    12          // 3 gates x 4 units per CTA
#define NJP_     6           // column pairs per CTA
#define RGRP_    16          // reduction groups after shuffle fold
#define WROW_    12          // w2 floats per k-row (NON-duplicated)
#define FB_      (F_ * B_)
#define UB_      (U_ * B_)
#define RSZ_     (RGRP_ * NJP_ * 2 * B_)   // floats per rs buffer (12288)

// Scratch (static __device__ arrays: no allocation)
__device__ __align__(256) float g_f_all[(size_t)T_ * UB_]; // sigmoid(f_pre) [t][u][b]
__device__ __align__(256) float g_x[(size_t)T_ * FB_];     // x transposed [t][f][b]
__device__ __align__(256) float g_h[2][UB_];               // ping-pong h [u][b]
__device__ unsigned int g_bar;

__device__ __forceinline__ void fma2(unsigned long long& a, unsigned long long x,
                                     unsigned long long w) {
    asm("fma.rn.f32x2 %0, %1, %2, %0;" : "+l"(a) : "l"(x), "l"(w));
}
__device__ __forceinline__ unsigned long long pack2(float x) {
    unsigned long long r; asm("mov.b64 %0, {%1, %1};" : "=l"(r) : "f"(x)); return r;
}
__device__ __forceinline__ float2 up2(unsigned long long v) {
    float2 r; asm("mov.b64 {%0, %1}, %2;" : "=f"(r.x), "=f"(r.y) : "l"(v)); return r;
}
__device__ __forceinline__ float tanh_fast(float x) {
    float y; asm("tanh.approx.f32 %0, %1;" : "=f"(y) : "f"(x)); return y;
}
__device__ __forceinline__ float sigmoid_fast(float x) {
    return 0.5f * tanh_fast(0.5f * x) + 0.5f;
}

// 24 packed FMAs for one k-row: activation float4 (4 batches) x 12 cols (6 pairs)
#define ROW_FMA(AV, WROWP)                                                     \
{                                                                              \
    const ulonglong2* wr_ = (const ulonglong2*)(WROWP);                        \
    ulonglong2 wA_ = wr_[0], wB_ = wr_[1], wC_ = wr_[2];                       \
    unsigned long long a0_ = pack2((AV).x), a1_ = pack2((AV).y);               \
    unsigned long long a2_ = pack2((AV).z), a3_ = pack2((AV).w);               \
    fma2(acc[0][0], a0_, wA_.x); fma2(acc[0][1], a1_, wA_.x);                  \
    fma2(acc[0][2], a2_, wA_.x); fma2(acc[0][3], a3_, wA_.x);                  \
    fma2(acc[1][0], a0_, wA_.y); fma2(acc[1][1], a1_, wA_.y);                  \
    fma2(acc[1][2], a2_, wA_.y); fma2(acc[1][3], a3_, wA_.y);                  \
    fma2(acc[2][0], a0_, wB_.x); fma2(acc[2][1], a1_, wB_.x);                  \
    fma2(acc[2][2], a2_, wB_.x); fma2(acc[2][3], a3_, wB_.x);                  \
    fma2(acc[3][0], a0_, wB_.y); fma2(acc[3][1], a1_, wB_.y);                  \
    fma2(acc[3][2], a2_, wB_.y); fma2(acc[3][3], a3_, wB_.y);                  \
    fma2(acc[4][0], a0_, wC_.x); fma2(acc[4][1], a1_, wC_.x);                  \
    fma2(acc[4][2], a2_, wC_.x); fma2(acc[4][3], a3_, wC_.x);                  \
    fma2(acc[5][0], a0_, wC_.y); fma2(acc[5][1], a1_, wC_.y);                  \
    fma2(acc[5][2], a2_, wC_.y); fma2(acc[5][3], a3_, wC_.y);                  \
}

// fpre: f_all[t][u][b] = sigmoid(sig . fk + b_f); transposes x to g_x[t][f][b];
// resets barrier counter + initial h each launch (graph replays).
__global__ void fpre_kernel(const float* __restrict__ inputs,
                            const float* __restrict__ sig,
                            const float* __restrict__ fk,
                            const float* __restrict__ bias) {
    extern __shared__ float xs[];            // [256][65] transpose tile
    __shared__ float sig_s[B_][33];
    const int t = blockIdx.x, tid = threadIdx.x;
    if (t == 0 && tid == 0) g_bar = 0u;
    if (t < 128) g_h[0][t * 256 + tid] = 0.f;

    for (int i = tid; i < B_ * F_; i += 256) {
        int b = i >> 8, f = i & 255;
        xs[f * 65 + b] = inputs[((size_t)b * T_ + t) * F_ + f];
    }
    for (int i = tid; i < B_ * SIG_; i += 256) {
        int b = i / SIG_, d = i - b * SIG_;
        sig_s[b][d] = sig[((size_t)b * T_ + t) * SIG_ + d];
    }
    __syncthreads();
    for (int j = tid; j < FB_; j += 256) {
        int f = j >> 6, b = j & 63;
        g_x[(size_t)t * FB_ + j] = xs[f * 65 + b];
    }
    size_t base = (size_t)t * UB_;
    for (int idx = tid; idx < UB_; idx += 256) {
        int u = idx >> 6, b = idx & 63;
        float acc = bias[U_ + u];
        #pragma unroll
        for (int d = 0; d < SIG_; d++) acc += sig_s[b][d] * __ldg(&fk[d * U_ + u]);
        g_f_all[base + idx] = 1.f / (1.f + expf(-acc));
    }
}

// Persistent recurrence (R11 champion) with: non-finalize poller warp,
// comp-major rs planes (conflict-free finalize reads), early fval load.
__global__ void __launch_bounds__(THREADS_, 1)
lstm_kernel(const float* __restrict__ ik, const float* __restrict__ rk,
            const float* __restrict__ bias, float* __restrict__ out) {
    extern __shared__ float smem[];
    float* w2  = smem;                         // [768][12] weights (36864 B)
    float* rs0 = smem + KTOT_ * WROW_;         // rs parity 0 (49152 B)
    float* rs1 = rs0 + RSZ_;                   // rs parity 1 (49152 B)

    const int tid  = threadIdx.x;
    const int ublk = blockIdx.x * 4;

    // Weights (non-duplicated): rows 0..255 = input_kernel, 256..767 = recurrent.
    for (int idx = tid; idx < KTOT_ * NCOL_; idx += THREADS_) {
        int k = idx / NCOL_, j = idx - k * NCOL_;
        int col = (j >> 2) * U_ + ublk + (j & 3);
        w2[idx] = (k < F_) ? ik[(size_t)k * G3_ + col]
                           : rk[(size_t)(k - F_) * G3_ + col];
    }

    const int b4 = tid & 15;            // batch group (4 batches)
    const int ks = tid >> 4;            // 0..31 K-split
    const int fb = tid & 63, fu = (tid >> 6) & 3;
    const int u_g = ublk + fu;
    float bi = 0.f, bc = 0.f, bo = 0.f;
    if (tid < 256) {
        bi = bias[u_g]; bc = bias[2 * U_ + u_g]; bo = bias[3 * U_ + u_g];
    }
    // finalize rs addressing: col j = gate*4 + fu -> pair jp = gate*2 + (fu>>1),
    // component fu&1; comp-major planes -> stride-1 in fb (conflict-free).
    const int fjp = fu >> 1, fcomp = fu & 1;

    const float* xbase = g_x + (size_t)(ks * 8) * B_ + b4 * 4;     // + t*FB_
    const int    hoff  = (ks * 16) * B_ + b4 * 4;                  // within g_h[p]
    const float* wx    = w2 + (ks * 8) * WROW_;
    const float* wh    = w2 + (F_ + ks * 16) * WROW_;

    float c_state = 0.f;
    float fval = (tid < 256) ? __ldg(&g_f_all[(size_t)u_g * B_ + fb]) : 0.f;
    __syncthreads();   // weights visible

    for (int t = 0; t < T_; t++) {
        unsigned long long acc[NJP_][4];
        #pragma unroll
        for (int j = 0; j < NJP_; j++) {
            acc[j][0] = 0ull; acc[j][1] = 0ull; acc[j][2] = 0ull; acc[j][3] = 0ull;
        }

        const float* xp = xbase + (size_t)t * FB_;
        const float* hp = g_h[t & 1] + hoff;
        float* rs = (t & 1) ? rs1 : rs0;

        // ---- Phase A: x-part; a NON-finalize warp (15) polls the barrier so
        //      the spin overlaps this CTA's own finalize/arrive of step t-1 ----
        float4 xv[8];
        #pragma unroll
        for (int j = 0; j < 8; j++) xv[j] = __ldg((const float4*)(xp + j * B_));
        if (tid == 480 && t > 0) {
            const unsigned tgt = (unsigned)t * GRID_;
            unsigned v;
            do {
                asm volatile("ld.acquire.gpu.global.u32 %0, [%1];"
                             : "=r"(v) : "l"(&g_bar) : "memory");
            } while (v < tgt);
        }
        #pragma unroll
        for (int j = 0; j < 4; j++) ROW_FMA(xv[j], wx + j * WROW_)
        __syncthreads();   // poll done -> h(t) globally visible

        // ---- Phase B: issue h loads, consume rest of x, then h ----
        float4 hv0[8], hv1[8];
        #pragma unroll
        for (int j = 0; j < 8; j++) hv0[j] = __ldcg((const float4*)(hp + j * B_));
        #pragma unroll
        for (int j = 0; j < 8; j++) hv1[j] = __ldcg((const float4*)(hp + (8 + j) * B_));
        #pragma unroll
        for (int j = 4; j < 8; j++) ROW_FMA(xv[j], wx + j * WROW_)
        #pragma unroll
        for (int j = 0; j < 8; j++) ROW_FMA(hv0[j], wh + j * WROW_)
        #pragma unroll
        for (int j = 0; j < 8; j++) ROW_FMA(hv1[j], wh + (8 + j) * WROW_)

        // ---- Phase C: shuffle-fold ks pairs (lane^16); comp-major planes ----
        #pragma unroll
        for (int jp = 0; jp < NJP_; jp++) {
            #pragma unroll
            for (int b = 0; b < 4; b++) {
                float2 v = up2(acc[jp][b]);
                v.x += __shfl_xor_sync(0xffffffffu, v.x, 16);
                v.y += __shfl_xor_sync(0xffffffffu, v.y, 16);
                if ((ks & 1) == 0) {
                    int base = (((ks >> 1) * NJP_ + jp) * 2) * B_ + b4 * 4 + b;
                    rs[base      ] = v.x;
                    rs[base + B_ ] = v.y;
                }
            }
        }
        __syncthreads();   // rs visible to finalize threads

        // ---- Phase D: finalize (tid<256); others run ahead into next x-part ----
        if (tid < 256) {
            float si = 0.f, sc = 0.f, so = 0.f;
            #pragma unroll
            for (int p = 0; p < RGRP_; p++) {
                si += rs[((p * NJP_     + fjp) * 2 + fcomp) * B_ + fb];
                sc += rs[((p * NJP_ + 2 + fjp) * 2 + fcomp) * B_ + fb];
                so += rs[((p * NJP_ + 4 + fjp) * 2 + fcomp) * B_ + fb];
            }
            float fnext = 0.f;
            if (t < T_ - 1)
                fnext = __ldg(&g_f_all[(size_t)(t + 1) * UB_ + u_g * B_ + fb]);
            float ig = sigmoid_fast(si + bi);
            float cg = tanh_fast(sc + bc);
            float og = sigmoid_fast(so + bo);
            c_state = fval * c_state + ig * cg;
            float h = og * tanh_fast(c_state);
            if (t == T_ - 1) {
                out[fb * U_ + u_g] = h;
            } else {
                g_h[(t + 1) & 1][u_g * B_ + fb] = h;
                fval = fnext;
                asm volatile("bar.sync 1, 256;" ::: "memory");  // all h stores done
                if (tid == 0) {
                    asm volatile("red.release.gpu.global.add.u32 [%0], %1;"
                                 :: "l"(&g_bar), "r"(1u) : "memory");
                }
            }
        }
        // no trailing sync: rs double-buffered; next phase-A sync re-converges.
    }
}

extern "C" void kernel_launch(void* const* d_in, const int* in_sizes, int n_in,
                              void* d_out, int out_size) {
    const float* inputs = (const float*)d_in[0];  // [64,1024,256]
    const float* sig    = (const float*)d_in[1];  // [64,1024,31]
    const float* fk     = (const float*)d_in[2];  // [31,512]
    const float* ik     = (const float*)d_in[3];  // [256,1536]
    const float* rk     = (const float*)d_in[4];  // [512,1536]
    const float* bias   = (const float*)d_in[5];  // [2048]
    float* out = (float*)d_out;                   // [64,512]
    (void)in_sizes; (void)n_in; (void)out_size;

    const int fpre_smem = 256 * 65 * 4;
    cudaFuncSetAttribute(fpre_kernel, cudaFuncAttributeMaxDynamicSharedMemorySize,
                         fpre_smem);
    const int smem_bytes = (KTOT_ * WROW_ + 2 * RSZ_) * 4;  // 135168 B
    cudaFuncSetAttribute(lstm_kernel, cudaFuncAttributeMaxDynamicSharedMemorySize,
                         smem_bytes);

    fpre_kernel<<<T_, 256, fpre_smem>>>(inputs, sig, fk, bias);
    lstm_kernel<<<GRID_, THREADS_, smem_bytes>>>(ik, rk, bias, out);
}